// round 1
// baseline (speedup 1.0000x reference)
#include <cuda_runtime.h>
#include <math.h>

#define NB   2
#define NC   256
#define NHW  2304     // 48*48
#define NCH  12

#define TI   12       // gray pixels per block (attention)
#define TIW  3        // gray pixels per warp
#define TJ   32       // rgb pixels per smem tile
#define RSTR 260      // padded row stride (floats) for rn tile

// ---------------- scratch (__device__ globals; no runtime alloc) ----------------
__device__ int   d_cls_g[NB * NHW];
__device__ int   d_cls_r[NB * NHW];
__device__ int   d_list_g[NB * NCH * NHW];
__device__ int   d_list_r[NB * NCH * NHW];
__device__ int   d_cnt_g[NB * NCH];
__device__ int   d_cnt_r[NB * NCH];
__device__ float d_mean_g[NB * NCH * NC];
__device__ float d_mean_r[NB * NCH * NC];
__device__ float d_gn[NB * NHW * NC];   // unit vectors, [b][n][c] (c contiguous)
__device__ float d_rn[NB * NHW * NC];

// ---------------- kernel 0: init output canvas to -1 ----------------
__global__ void k_init(float* out, int n) {
    int i = blockIdx.x * blockDim.x + threadIdx.x;
    if (i < n) out[i] = -1.0f;
}

// ---------------- kernel 1: per-pixel class from one-hot labels ----------------
__global__ void k_classify(const float* __restrict__ gl, const float* __restrict__ rl) {
    int idx = blockIdx.x * blockDim.x + threadIdx.x;   // b*NHW + n
    if (idx >= NB * NHW) return;
    int b = idx / NHW, n = idx - b * NHW;
    int kg = 0, kr = 0;
#pragma unroll
    for (int k = 0; k < NCH; k++) {
        if (gl[(b * NCH + k) * NHW + n] > 0.5f) kg = k;
        if (rl[(b * NCH + k) * NHW + n] > 0.5f) kr = k;
    }
    d_cls_g[idx] = kg;
    d_cls_r[idx] = kr;
}

// ---------------- kernel 2: ordered compaction into per-(b,k) pixel lists ----------------
__global__ void k_lists() {
    int k = blockIdx.x, b = blockIdx.y;
    int tid = threadIdx.x, lane = tid & 31, w = tid >> 5;
    __shared__ int s_wsum[8];
    const int* clsg = d_cls_g + b * NHW;
    const int* clsr = d_cls_r + b * NHW;
    int* lg = d_list_g + (b * NCH + k) * NHW;
    int* lr = d_list_r + (b * NCH + k) * NHW;
    int base_g = 0, base_r = 0;
    for (int n0 = 0; n0 < NHW; n0 += 256) {
        int n = n0 + tid;
        // gray
        int fg = (n < NHW) && (clsg[n] == k);
        unsigned bal = __ballot_sync(0xffffffffu, fg);
        int wp = __popc(bal & ((1u << lane) - 1u));
        if (lane == 0) s_wsum[w] = __popc(bal);
        __syncthreads();
        int woff = 0, tot = 0;
#pragma unroll
        for (int i = 0; i < 8; i++) { int v = s_wsum[i]; if (i < w) woff += v; tot += v; }
        if (fg) lg[base_g + woff + wp] = n;
        base_g += tot;
        __syncthreads();
        // rgb
        int fr = (n < NHW) && (clsr[n] == k);
        bal = __ballot_sync(0xffffffffu, fr);
        wp = __popc(bal & ((1u << lane) - 1u));
        if (lane == 0) s_wsum[w] = __popc(bal);
        __syncthreads();
        woff = 0; tot = 0;
#pragma unroll
        for (int i = 0; i < 8; i++) { int v = s_wsum[i]; if (i < w) woff += v; tot += v; }
        if (fr) lr[base_r + woff + wp] = n;
        base_r += tot;
        __syncthreads();
    }
    if (tid == 0) { d_cnt_g[b * NCH + k] = base_g; d_cnt_r[b * NCH + k] = base_r; }
}

// ---------------- kernel 3: per-(b,k,c) masked means ----------------
__global__ void k_means(const float* __restrict__ gf, const float* __restrict__ rf) {
    int bc = blockIdx.x;
    int b = bc / NC, c = bc - b * NC;
    const float* g = gf + (b * NC + c) * NHW;
    const float* r = rf + (b * NC + c) * NHW;
    const int* cg = d_cls_g + b * NHW;
    const int* cr = d_cls_r + b * NHW;
    float sg[NCH], sr[NCH];
#pragma unroll
    for (int k = 0; k < NCH; k++) { sg[k] = 0.f; sr[k] = 0.f; }
    for (int n = threadIdx.x; n < NHW; n += 256) {
        float vg = g[n], vr = r[n];
        int kg = cg[n], kr = cr[n];
#pragma unroll
        for (int k = 0; k < NCH; k++) {
            sg[k] += (kg == k) ? vg : 0.f;
            sr[k] += (kr == k) ? vr : 0.f;
        }
    }
#pragma unroll
    for (int k = 0; k < NCH; k++) {
#pragma unroll
        for (int off = 16; off; off >>= 1) {
            sg[k] += __shfl_xor_sync(0xffffffffu, sg[k], off);
            sr[k] += __shfl_xor_sync(0xffffffffu, sr[k], off);
        }
    }
    __shared__ float sm[8][2 * NCH];
    int lane = threadIdx.x & 31, w = threadIdx.x >> 5;
    if (lane == 0) {
#pragma unroll
        for (int k = 0; k < NCH; k++) { sm[w][k] = sg[k]; sm[w][NCH + k] = sr[k]; }
    }
    __syncthreads();
    if (threadIdx.x < 2 * NCH) {
        float t = 0.f;
#pragma unroll
        for (int i = 0; i < 8; i++) t += sm[i][threadIdx.x];
        int k = threadIdx.x % NCH;
        bool isr = threadIdx.x >= NCH;
        int cnt = isr ? d_cnt_r[b * NCH + k] : d_cnt_g[b * NCH + k];
        float mean = t / fmaxf((float)cnt, 1.f);
        if (isr) d_mean_r[(b * NCH + k) * NC + c] = mean;
        else     d_mean_g[(b * NCH + k) * NC + c] = mean;
    }
}

// ---------------- kernel 4: normalize + transpose to [b][n][c] ----------------
__global__ void k_normalize(const float* __restrict__ gf, const float* __restrict__ rf) {
    __shared__ float tile[NC][33];
    int b = blockIdx.y;
    int n0 = blockIdx.x * 32;
    int tid = threadIdx.x, lane = tid & 31, w = tid >> 5;
    for (int p = 0; p < 2; p++) {
        const float* f   = (p == 0 ? gf : rf) + b * NC * NHW;
        const int*  cls  = (p == 0 ? d_cls_g : d_cls_r) + b * NHW;
        const float* mn  = (p == 0 ? d_mean_g : d_mean_r) + b * NCH * NC;
        float* outp      = (p == 0 ? d_gn : d_rn) + b * NHW * NC;
        __syncthreads();
        for (int idx = tid; idx < NC * 32; idx += 256) {
            int c = idx >> 5, nn = idx & 31;
            tile[c][nn] = f[c * NHW + n0 + nn];
        }
        __syncthreads();
#pragma unroll
        for (int q = 0; q < 4; q++) {
            int nn = w * 4 + q;
            int n = n0 + nn;
            int k = cls[n];
            const float* mk = mn + k * NC;
            float bar[8]; float ss = 0.f;
#pragma unroll
            for (int t = 0; t < 8; t++) {
                int c = lane + 32 * t;
                float v = tile[c][nn] - mk[c];
                bar[t] = v;
                ss += v * v;
            }
#pragma unroll
            for (int off = 16; off; off >>= 1) ss += __shfl_xor_sync(0xffffffffu, ss, off);
            float norm = sqrtf(ss);
            float inv = (norm > 0.f) ? (1.f / norm) : 1.f;
#pragma unroll
            for (int t = 0; t < 8; t++)
                outp[n * NC + lane + 32 * t] = bar[t] * inv;
        }
    }
}

// ---------------- kernel 5: attention (online softmax, lane-per-j, 3 i per warp) ----------------
__global__ void __launch_bounds__(128) k_attn(const float* __restrict__ img, float* __restrict__ out) {
    __shared__ __align__(16) float rn_s[TJ * RSTR];   // 33280 B
    __shared__ __align__(16) float gn_s[TI * NC];     // 12288 B
    __shared__ float img_s[TJ * 3];
    __shared__ int s_jl[TJ];
    __shared__ int s_pix[TI];

    int k = blockIdx.y + 1;
    int b = blockIdx.z;
    int cg = d_cnt_g[b * NCH + k], cr = d_cnt_r[b * NCH + k];
    if (cg < 2 || cr < 2) return;                 // invalid class: canvas stays -1
    int i_base = blockIdx.x * TI;
    if (i_base >= cg) return;

    int tid = threadIdx.x, lane = tid & 31, w = tid >> 5;
    const int* lg = d_list_g + (b * NCH + k) * NHW;
    const int* lr = d_list_r + (b * NCH + k) * NHW;
    const float* gn = d_gn + b * NHW * NC;
    const float* rn = d_rn + b * NHW * NC;
    const float* imgb = img + b * 3 * NHW;

    if (tid < TI) s_pix[tid] = lg[min(i_base + tid, cg - 1)];
    __syncthreads();
    for (int idx = tid; idx < TI * NC; idx += 128) {
        int row = idx >> 8, col = idx & 255;
        gn_s[idx] = gn[s_pix[row] * NC + col];
    }

    float m[TIW], sden[TIW], a0[TIW], a1[TIW], a2[TIW];
#pragma unroll
    for (int ii = 0; ii < TIW; ii++) { m[ii] = -1e30f; sden[ii] = 0.f; a0[ii] = 0.f; a1[ii] = 0.f; a2[ii] = 0.f; }

    for (int j0 = 0; j0 < cr; j0 += TJ) {
        int jcnt = min(TJ, cr - j0);
        __syncthreads();
        if (tid < TJ) s_jl[tid] = (tid < jcnt) ? lr[j0 + tid] : -1;
        __syncthreads();
        for (int idx = tid; idx < TJ * NC; idx += 128) {
            int row = idx >> 8, col = idx & 255;
            int jp = s_jl[row];
            rn_s[row * RSTR + col] = (jp >= 0) ? rn[jp * NC + col] : 0.f;
        }
        if (tid < 96) {
            int cc = tid >> 5, jj = tid & 31;
            int jp = s_jl[jj];
            img_s[jj * 3 + cc] = (jp >= 0) ? imgb[cc * NHW + jp] : 0.f;
        }
        __syncthreads();

        float d0 = 0.f, d1 = 0.f, d2 = 0.f;
        const float4* rr = (const float4*)(rn_s + lane * RSTR);
        const float4* g0 = (const float4*)(gn_s + (w * TIW + 0) * NC);
        const float4* g1 = (const float4*)(gn_s + (w * TIW + 1) * NC);
        const float4* g2 = (const float4*)(gn_s + (w * TIW + 2) * NC);
#pragma unroll 8
        for (int c4 = 0; c4 < NC / 4; c4++) {
            float4 r = rr[c4];
            float4 x0 = g0[c4], x1 = g1[c4], x2 = g2[c4];
            d0 += r.x * x0.x + r.y * x0.y + r.z * x0.z + r.w * x0.w;
            d1 += r.x * x1.x + r.y * x1.y + r.z * x1.z + r.w * x1.w;
            d2 += r.x * x2.x + r.y * x2.y + r.z * x2.z + r.w * x2.w;
        }
        if (lane < jcnt) {
            float iv0 = img_s[lane * 3 + 0];
            float iv1 = img_s[lane * 3 + 1];
            float iv2 = img_s[lane * 3 + 2];
            float dd[TIW] = { d0, d1, d2 };
#pragma unroll
            for (int ii = 0; ii < TIW; ii++) {
                float d = dd[ii];
                float nm = fmaxf(m[ii], d);
                float sc = __expf(m[ii] - nm);
                float e  = __expf(d - nm);
                sden[ii] = sden[ii] * sc + e;
                a0[ii] = a0[ii] * sc + e * iv0;
                a1[ii] = a1[ii] * sc + e * iv1;
                a2[ii] = a2[ii] * sc + e * iv2;
                m[ii] = nm;
            }
        }
    }

    // cross-lane merge of online-softmax states, then write
#pragma unroll
    for (int ii = 0; ii < TIW; ii++) {
        float m_ = m[ii], s_ = sden[ii], x = a0[ii], y = a1[ii], z = a2[ii];
#pragma unroll
        for (int off = 16; off; off >>= 1) {
            float m2 = __shfl_xor_sync(0xffffffffu, m_, off);
            float s2 = __shfl_xor_sync(0xffffffffu, s_, off);
            float x2 = __shfl_xor_sync(0xffffffffu, x, off);
            float y2 = __shfl_xor_sync(0xffffffffu, y, off);
            float z2 = __shfl_xor_sync(0xffffffffu, z, off);
            float M  = fmaxf(m_, m2);
            float c1 = __expf(m_ - M), c2 = __expf(m2 - M);
            s_ = s_ * c1 + s2 * c2;
            x  = x  * c1 + x2 * c2;
            y  = y  * c1 + y2 * c2;
            z  = z  * c1 + z2 * c2;
            m_ = M;
        }
        int ig = i_base + w * TIW + ii;
        if (lane == 0 && ig < cg) {
            int pix = s_pix[w * TIW + ii];
            float inv = 1.f / s_;
            out[b * 3 * NHW + 0 * NHW + pix] = x * inv;
            out[b * 3 * NHW + 1 * NHW + pix] = y * inv;
            out[b * 3 * NHW + 2 * NHW + pix] = z * inv;
        }
    }
}

// ---------------- launch ----------------
extern "C" void kernel_launch(void* const* d_in, const int* in_sizes, int n_in,
                              void* d_out, int out_size) {
    (void)in_sizes; (void)n_in;
    const float* gf  = (const float*)d_in[0];
    const float* rf  = (const float*)d_in[1];
    const float* img = (const float*)d_in[2];
    const float* gl  = (const float*)d_in[3];
    const float* rl  = (const float*)d_in[4];
    float* out = (float*)d_out;

    k_init<<<(out_size + 255) / 256, 256>>>(out, out_size);
    k_classify<<<(NB * NHW + 255) / 256, 256>>>(gl, rl);
    k_lists<<<dim3(NCH, NB), 256>>>();
    k_means<<<NB * NC, 256>>>(gf, rf);
    k_normalize<<<dim3(NHW / 32, NB), 256>>>(gf, rf);
    k_attn<<<dim3((NHW + TI - 1) / TI, NCH - 1, NB), 128>>>(img, out);
}

// round 2
// speedup vs baseline: 1.9431x; 1.9431x over previous
#include <cuda_runtime.h>
#include <math.h>

#define NB   2
#define NC   256
#define NHW  2304     // 48*48
#define NCH  12

#define TI   16       // gray pixels per block (attention)
#define TIW  4        // gray pixels per warp
#define TJ   32       // rgb pixels per smem tile
#define RSTR 260      // padded row stride (floats) for rn tile (260*4B%16==0, conflict-free)

// ---------------- scratch (__device__ globals; no runtime alloc) ----------------
__device__ int   d_cls_g[NB * NHW];
__device__ int   d_cls_r[NB * NHW];
__device__ int   d_list_g[NB * NCH * NHW];
__device__ int   d_list_r[NB * NCH * NHW];
__device__ int   d_cnt_g[NB * NCH];
__device__ int   d_cnt_r[NB * NCH];
__device__ float d_mean_g[NB * NCH * NC];
__device__ float d_mean_r[NB * NCH * NC];
__device__ float d_gn[NB * NHW * NC];   // unit vectors, [b][n][c] (c contiguous)
__device__ float d_rn[NB * NHW * NC];

// ---------------- kernel 1: classify pixels (float4 over 4 pixels) + init canvas ----------------
__global__ void k_classify(const float* __restrict__ gl, const float* __restrict__ rl,
                           float* __restrict__ out) {
    int idx = blockIdx.x * blockDim.x + threadIdx.x;   // over NB*NHW/4
    if (idx >= NB * NHW / 4) return;
    // fold canvas init: 3456 float4 of -1; exactly 3 per thread
    float4 neg = make_float4(-1.f, -1.f, -1.f, -1.f);
    float4* o4 = (float4*)out;
#pragma unroll
    for (int t = 0; t < 3; t++) o4[idx + t * (NB * NHW / 4)] = neg;

    int b = idx / (NHW / 4), n4 = idx - b * (NHW / 4);
    int kg0 = 0, kg1 = 0, kg2 = 0, kg3 = 0;
    int kr0 = 0, kr1 = 0, kr2 = 0, kr3 = 0;
#pragma unroll
    for (int k = 0; k < NCH; k++) {
        float4 g = ((const float4*)(gl + (b * NCH + k) * NHW))[n4];
        float4 r = ((const float4*)(rl + (b * NCH + k) * NHW))[n4];
        if (g.x > 0.5f) kg0 = k;  if (g.y > 0.5f) kg1 = k;
        if (g.z > 0.5f) kg2 = k;  if (g.w > 0.5f) kg3 = k;
        if (r.x > 0.5f) kr0 = k;  if (r.y > 0.5f) kr1 = k;
        if (r.z > 0.5f) kr2 = k;  if (r.w > 0.5f) kr3 = k;
    }
    ((int4*)d_cls_g)[b * (NHW / 4) + n4] = make_int4(kg0, kg1, kg2, kg3);
    ((int4*)d_cls_r)[b * (NHW / 4) + n4] = make_int4(kr0, kr1, kr2, kr3);
}

// ---------------- kernel 2: ordered compaction into per-(b,k) pixel lists ----------------
__global__ void k_lists() {
    int k = blockIdx.x, b = blockIdx.y;
    int tid = threadIdx.x, lane = tid & 31, w = tid >> 5;
    __shared__ int s_wsum[16];
    const int* clsg = d_cls_g + b * NHW;
    const int* clsr = d_cls_r + b * NHW;
    int* lg = d_list_g + (b * NCH + k) * NHW;
    int* lr = d_list_r + (b * NCH + k) * NHW;
    int base_g = 0, base_r = 0;
    for (int n0 = 0; n0 < NHW; n0 += 512) {
        int n = n0 + tid;
        int fg = (n < NHW) && (clsg[n] == k);
        unsigned bal = __ballot_sync(0xffffffffu, fg);
        int wp = __popc(bal & ((1u << lane) - 1u));
        if (lane == 0) s_wsum[w] = __popc(bal);
        __syncthreads();
        int woff = 0, tot = 0;
#pragma unroll
        for (int i = 0; i < 16; i++) { int v = s_wsum[i]; if (i < w) woff += v; tot += v; }
        if (fg) lg[base_g + woff + wp] = n;
        base_g += tot;
        __syncthreads();
        int fr = (n < NHW) && (clsr[n] == k);
        bal = __ballot_sync(0xffffffffu, fr);
        wp = __popc(bal & ((1u << lane) - 1u));
        if (lane == 0) s_wsum[w] = __popc(bal);
        __syncthreads();
        woff = 0; tot = 0;
#pragma unroll
        for (int i = 0; i < 16; i++) { int v = s_wsum[i]; if (i < w) woff += v; tot += v; }
        if (fr) lr[base_r + woff + wp] = n;
        base_r += tot;
        __syncthreads();
    }
    if (tid == 0) { d_cnt_g[b * NCH + k] = base_g; d_cnt_r[b * NCH + k] = base_r; }
}

// ---------------- kernel 3: per-(b,k,c) masked means (float4 / int4) ----------------
__global__ void k_means(const float* __restrict__ gf, const float* __restrict__ rf) {
    int bc = blockIdx.x;
    int b = bc / NC, c = bc - b * NC;
    const float4* g4 = (const float4*)(gf + (b * NC + c) * NHW);
    const float4* r4 = (const float4*)(rf + (b * NC + c) * NHW);
    const int4* cg4 = (const int4*)(d_cls_g + b * NHW);
    const int4* cr4 = (const int4*)(d_cls_r + b * NHW);
    float sg[NCH], sr[NCH];
#pragma unroll
    for (int k = 0; k < NCH; k++) { sg[k] = 0.f; sr[k] = 0.f; }
    for (int q = threadIdx.x; q < NHW / 4; q += 256) {
        float4 vg = g4[q], vr = r4[q];
        int4 kg = cg4[q], kr = cr4[q];
#pragma unroll
        for (int k = 0; k < NCH; k++) {
            sg[k] += (kg.x == k) ? vg.x : 0.f;
            sg[k] += (kg.y == k) ? vg.y : 0.f;
            sg[k] += (kg.z == k) ? vg.z : 0.f;
            sg[k] += (kg.w == k) ? vg.w : 0.f;
            sr[k] += (kr.x == k) ? vr.x : 0.f;
            sr[k] += (kr.y == k) ? vr.y : 0.f;
            sr[k] += (kr.z == k) ? vr.z : 0.f;
            sr[k] += (kr.w == k) ? vr.w : 0.f;
        }
    }
#pragma unroll
    for (int k = 0; k < NCH; k++) {
#pragma unroll
        for (int off = 16; off; off >>= 1) {
            sg[k] += __shfl_xor_sync(0xffffffffu, sg[k], off);
            sr[k] += __shfl_xor_sync(0xffffffffu, sr[k], off);
        }
    }
    __shared__ float sm[8][2 * NCH];
    int lane = threadIdx.x & 31, w = threadIdx.x >> 5;
    if (lane == 0) {
#pragma unroll
        for (int k = 0; k < NCH; k++) { sm[w][k] = sg[k]; sm[w][NCH + k] = sr[k]; }
    }
    __syncthreads();
    if (threadIdx.x < 2 * NCH) {
        float t = 0.f;
#pragma unroll
        for (int i = 0; i < 8; i++) t += sm[i][threadIdx.x];
        int k = threadIdx.x % NCH;
        bool isr = threadIdx.x >= NCH;
        int cnt = isr ? d_cnt_r[b * NCH + k] : d_cnt_g[b * NCH + k];
        float mean = t / fmaxf((float)cnt, 1.f);
        if (isr) d_mean_r[(b * NCH + k) * NC + c] = mean;
        else     d_mean_g[(b * NCH + k) * NC + c] = mean;
    }
}

// ---------------- kernel 4: normalize + transpose to [b][n][c] ----------------
__global__ void k_normalize(const float* __restrict__ gf, const float* __restrict__ rf) {
    __shared__ float tile[NC][33];
    int b = blockIdx.y;
    int n0 = blockIdx.x * 32;
    int tid = threadIdx.x, lane = tid & 31, w = tid >> 5;
#pragma unroll
    for (int p = 0; p < 2; p++) {
        const float* f   = (p == 0 ? gf : rf) + b * NC * NHW;
        const int*  cls  = (p == 0 ? d_cls_g : d_cls_r) + b * NHW;
        const float* mn  = (p == 0 ? d_mean_g : d_mean_r) + b * NCH * NC;
        float* outp      = (p == 0 ? d_gn : d_rn) + b * NHW * NC;
        __syncthreads();
        // fill: 256 rows x 8 float4 = 2048 vec loads, 8 per thread
#pragma unroll
        for (int it = 0; it < 8; it++) {
            int idx = tid + it * 256;
            int c = idx >> 3, q = idx & 7;
            float4 v = ((const float4*)(f + c * NHW + n0))[q];
            tile[c][q * 4 + 0] = v.x;
            tile[c][q * 4 + 1] = v.y;
            tile[c][q * 4 + 2] = v.z;
            tile[c][q * 4 + 3] = v.w;
        }
        __syncthreads();
#pragma unroll
        for (int q = 0; q < 4; q++) {
            int nn = w * 4 + q;
            int n = n0 + nn;
            int k = cls[n];
            const float* mk = mn + k * NC;
            float bar[8]; float ss = 0.f;
#pragma unroll
            for (int t = 0; t < 8; t++) {
                int c = lane + 32 * t;
                float v = tile[c][nn] - mk[c];
                bar[t] = v;
                ss += v * v;
            }
#pragma unroll
            for (int off = 16; off; off >>= 1) ss += __shfl_xor_sync(0xffffffffu, ss, off);
            float norm = sqrtf(ss);
            float inv = (norm > 0.f) ? (1.f / norm) : 1.f;
#pragma unroll
            for (int t = 0; t < 8; t++)
                outp[n * NC + lane + 32 * t] = bar[t] * inv;
        }
    }
}

// ---------------- kernel 5: attention (online softmax, lane-per-j, 4 i per warp) ----------------
__global__ void __launch_bounds__(128) k_attn(const float* __restrict__ img, float* __restrict__ out) {
    __shared__ __align__(16) float rn_s[TJ * RSTR];   // 33280 B
    __shared__ __align__(16) float gn_s[TI * NC];     // 16384 B
    __shared__ float img_s[TJ * 3];
    __shared__ int s_jl[TJ];
    __shared__ int s_pix[TI];

    int k = blockIdx.y + 1;
    int b = blockIdx.z;
    int cg = d_cnt_g[b * NCH + k], cr = d_cnt_r[b * NCH + k];
    if (cg < 2 || cr < 2) return;                 // invalid class: canvas stays -1
    int i_base = blockIdx.x * TI;
    if (i_base >= cg) return;

    int tid = threadIdx.x, lane = tid & 31, w = tid >> 5;
    const int* lg = d_list_g + (b * NCH + k) * NHW;
    const int* lr = d_list_r + (b * NCH + k) * NHW;
    const float4* gn4 = (const float4*)(d_gn + b * NHW * NC);
    const float4* rn4 = (const float4*)(d_rn + b * NHW * NC);
    const float* imgb = img + b * 3 * NHW;

    if (tid < TI) s_pix[tid] = lg[min(i_base + tid, cg - 1)];
    __syncthreads();
    // gn tile: TI*64 float4 = 1024, 8 per thread
#pragma unroll
    for (int it = 0; it < (TI * 64) / 128; it++) {
        int idx = tid + it * 128;
        int row = idx >> 6, col4 = idx & 63;
        ((float4*)gn_s)[idx] = gn4[s_pix[row] * 64 + col4];
    }

    float m[TIW], sden[TIW], a0[TIW], a1[TIW], a2[TIW];
#pragma unroll
    for (int ii = 0; ii < TIW; ii++) { m[ii] = -1e30f; sden[ii] = 0.f; a0[ii] = 0.f; a1[ii] = 0.f; a2[ii] = 0.f; }

    for (int j0 = 0; j0 < cr; j0 += TJ) {
        int jcnt = min(TJ, cr - j0);
        __syncthreads();
        if (tid < TJ) s_jl[tid] = (tid < jcnt) ? lr[j0 + tid] : -1;
        __syncthreads();
        // rn tile: 32*64 float4 = 2048, 16 per thread
#pragma unroll
        for (int it = 0; it < 16; it++) {
            int idx = tid + it * 128;
            int row = idx >> 6, col4 = idx & 63;
            int jp = s_jl[row];
            float4 v = (jp >= 0) ? rn4[jp * 64 + col4] : make_float4(0.f, 0.f, 0.f, 0.f);
            *(float4*)(rn_s + row * RSTR + col4 * 4) = v;
        }
        if (tid < 96) {
            int cc = tid >> 5, jj = tid & 31;
            int jp = s_jl[jj];
            img_s[jj * 3 + cc] = (jp >= 0) ? imgb[cc * NHW + jp] : 0.f;
        }
        __syncthreads();

        float d0 = 0.f, d1 = 0.f, d2 = 0.f, d3 = 0.f;
        const float4* rr = (const float4*)(rn_s + lane * RSTR);
        const float4* g0 = (const float4*)(gn_s + (w * TIW + 0) * NC);
        const float4* g1 = (const float4*)(gn_s + (w * TIW + 1) * NC);
        const float4* g2 = (const float4*)(gn_s + (w * TIW + 2) * NC);
        const float4* g3 = (const float4*)(gn_s + (w * TIW + 3) * NC);
#pragma unroll 4
        for (int c4 = 0; c4 < NC / 4; c4++) {
            float4 r = rr[c4];
            float4 x0 = g0[c4], x1 = g1[c4], x2 = g2[c4], x3 = g3[c4];
            d0 += r.x * x0.x + r.y * x0.y + r.z * x0.z + r.w * x0.w;
            d1 += r.x * x1.x + r.y * x1.y + r.z * x1.z + r.w * x1.w;
            d2 += r.x * x2.x + r.y * x2.y + r.z * x2.z + r.w * x2.w;
            d3 += r.x * x3.x + r.y * x3.y + r.z * x3.z + r.w * x3.w;
        }
        if (lane < jcnt) {
            float iv0 = img_s[lane * 3 + 0];
            float iv1 = img_s[lane * 3 + 1];
            float iv2 = img_s[lane * 3 + 2];
            float dd[TIW] = { d0, d1, d2, d3 };
#pragma unroll
            for (int ii = 0; ii < TIW; ii++) {
                float d = dd[ii];
                float nm = fmaxf(m[ii], d);
                float sc = __expf(m[ii] - nm);
                float e  = __expf(d - nm);
                sden[ii] = sden[ii] * sc + e;
                a0[ii] = a0[ii] * sc + e * iv0;
                a1[ii] = a1[ii] * sc + e * iv1;
                a2[ii] = a2[ii] * sc + e * iv2;
                m[ii] = nm;
            }
        }
    }

    // cross-lane merge of online-softmax states, then write
#pragma unroll
    for (int ii = 0; ii < TIW; ii++) {
        float m_ = m[ii], s_ = sden[ii], x = a0[ii], y = a1[ii], z = a2[ii];
#pragma unroll
        for (int off = 16; off; off >>= 1) {
            float m2 = __shfl_xor_sync(0xffffffffu, m_, off);
            float s2 = __shfl_xor_sync(0xffffffffu, s_, off);
            float x2 = __shfl_xor_sync(0xffffffffu, x, off);
            float y2 = __shfl_xor_sync(0xffffffffu, y, off);
            float z2 = __shfl_xor_sync(0xffffffffu, z, off);
            float M  = fmaxf(m_, m2);
            float c1 = __expf(m_ - M), c2 = __expf(m2 - M);
            s_ = s_ * c1 + s2 * c2;
            x  = x  * c1 + x2 * c2;
            y  = y  * c1 + y2 * c2;
            z  = z  * c1 + z2 * c2;
            m_ = M;
        }
        int ig = i_base + w * TIW + ii;
        if (lane == 0 && ig < cg) {
            int pix = s_pix[w * TIW + ii];
            float inv = 1.f / s_;
            out[b * 3 * NHW + 0 * NHW + pix] = x * inv;
            out[b * 3 * NHW + 1 * NHW + pix] = y * inv;
            out[b * 3 * NHW + 2 * NHW + pix] = z * inv;
        }
    }
}

// ---------------- launch ----------------
extern "C" void kernel_launch(void* const* d_in, const int* in_sizes, int n_in,
                              void* d_out, int out_size) {
    (void)in_sizes; (void)n_in; (void)out_size;
    const float* gf  = (const float*)d_in[0];
    const float* rf  = (const float*)d_in[1];
    const float* img = (const float*)d_in[2];
    const float* gl  = (const float*)d_in[3];
    const float* rl  = (const float*)d_in[4];
    float* out = (float*)d_out;

    k_classify<<<(NB * NHW / 4 + 255) / 256, 256>>>(gl, rl, out);
    k_lists<<<dim3(NCH, NB), 512>>>();
    k_means<<<NB * NC, 256>>>(gf, rf);
    k_normalize<<<dim3(NHW / 32, NB), 256>>>(gf, rf);
    k_attn<<<dim3((NHW + TI - 1) / TI, NCH - 1, NB), 128>>>(img, out);
}

// round 3
// speedup vs baseline: 2.2026x; 1.1336x over previous
#include <cuda_runtime.h>
#include <math.h>

#define NB   2
#define NC   256
#define NHW  2304     // 48*48
#define NCH  12

#define TI   16       // gray pixels per attention block
#define TIW  4        // gray pixels per warp
#define TJ   64       // rgb pixels per smem tile
#define RSTR 260      // padded row stride (floats), 1040B: 16B-aligned, conflict-free
#define GX   16       // attention grid.x (stride loop handles overflow)

#define ATTN_SMEM (TJ*RSTR*4 + TI*NC*4 + TJ*3*4 + TJ*4 + TI*4)

// ---------------- scratch ----------------
__device__ int   d_cls_g[NB * NHW];
__device__ int   d_cls_r[NB * NHW];
__device__ int   d_list_g[NB * NCH * NHW];
__device__ int   d_list_r[NB * NCH * NHW];
__device__ int   d_cnt_g[NB * NCH];
__device__ int   d_cnt_r[NB * NCH];
__device__ float d_mean_g[NB * NCH * NC];
__device__ float d_mean_r[NB * NCH * NC];
__device__ float d_gn[NB * NHW * NC];   // unit vectors, [b][n][c]
__device__ float d_rn[NB * NHW * NC];

// packed f32x2 fma: d += a*b elementwise on 2 packed floats
__device__ __forceinline__ void fma2(unsigned long long& d, unsigned long long a, unsigned long long b) {
    asm("fma.rn.f32x2 %0, %1, %2, %0;" : "+l"(d) : "l"(a), "l"(b));
}
__device__ __forceinline__ float hsum2(unsigned long long a, unsigned long long b) {
    unsigned long long s;
    asm("add.rn.f32x2 %0, %1, %2;" : "=l"(s) : "l"(a), "l"(b));
    float lo, hi;
    asm("mov.b64 {%0, %1}, %2;" : "=f"(lo), "=f"(hi) : "l"(s));
    return lo + hi;
}

// ---------------- kernel 1: classify + init canvas ----------------
__global__ void k_classify(const float* __restrict__ gl, const float* __restrict__ rl,
                           float* __restrict__ out) {
    int idx = blockIdx.x * blockDim.x + threadIdx.x;   // over NB*NHW/4
    if (idx >= NB * NHW / 4) return;
    float4 neg = make_float4(-1.f, -1.f, -1.f, -1.f);
    float4* o4 = (float4*)out;
#pragma unroll
    for (int t = 0; t < 3; t++) o4[idx + t * (NB * NHW / 4)] = neg;

    int b = idx / (NHW / 4), n4 = idx - b * (NHW / 4);
    int kg0 = 0, kg1 = 0, kg2 = 0, kg3 = 0;
    int kr0 = 0, kr1 = 0, kr2 = 0, kr3 = 0;
#pragma unroll
    for (int k = 0; k < NCH; k++) {
        float4 g = ((const float4*)(gl + (b * NCH + k) * NHW))[n4];
        float4 r = ((const float4*)(rl + (b * NCH + k) * NHW))[n4];
        if (g.x > 0.5f) kg0 = k;  if (g.y > 0.5f) kg1 = k;
        if (g.z > 0.5f) kg2 = k;  if (g.w > 0.5f) kg3 = k;
        if (r.x > 0.5f) kr0 = k;  if (r.y > 0.5f) kr1 = k;
        if (r.z > 0.5f) kr2 = k;  if (r.w > 0.5f) kr3 = k;
    }
    ((int4*)d_cls_g)[b * (NHW / 4) + n4] = make_int4(kg0, kg1, kg2, kg3);
    ((int4*)d_cls_r)[b * (NHW / 4) + n4] = make_int4(kr0, kr1, kr2, kr3);
}

// ---------------- kernel 2: ordered compaction ----------------
__global__ void k_lists() {
    int k = blockIdx.x, b = blockIdx.y;
    int tid = threadIdx.x, lane = tid & 31, w = tid >> 5;
    __shared__ int s_wsum[16];
    const int* clsg = d_cls_g + b * NHW;
    const int* clsr = d_cls_r + b * NHW;
    int* lg = d_list_g + (b * NCH + k) * NHW;
    int* lr = d_list_r + (b * NCH + k) * NHW;
    int base_g = 0, base_r = 0;
    for (int n0 = 0; n0 < NHW; n0 += 512) {
        int n = n0 + tid;
        int fg = (n < NHW) && (clsg[n] == k);
        unsigned bal = __ballot_sync(0xffffffffu, fg);
        int wp = __popc(bal & ((1u << lane) - 1u));
        if (lane == 0) s_wsum[w] = __popc(bal);
        __syncthreads();
        int woff = 0, tot = 0;
#pragma unroll
        for (int i = 0; i < 16; i++) { int v = s_wsum[i]; if (i < w) woff += v; tot += v; }
        if (fg) lg[base_g + woff + wp] = n;
        base_g += tot;
        __syncthreads();
        int fr = (n < NHW) && (clsr[n] == k);
        bal = __ballot_sync(0xffffffffu, fr);
        wp = __popc(bal & ((1u << lane) - 1u));
        if (lane == 0) s_wsum[w] = __popc(bal);
        __syncthreads();
        woff = 0; tot = 0;
#pragma unroll
        for (int i = 0; i < 16; i++) { int v = s_wsum[i]; if (i < w) woff += v; tot += v; }
        if (fr) lr[base_r + woff + wp] = n;
        base_r += tot;
        __syncthreads();
    }
    if (tid == 0) { d_cnt_g[b * NCH + k] = base_g; d_cnt_r[b * NCH + k] = base_r; }
}

// ---------------- kernel 3: per-(b,k,c) masked means ----------------
__global__ void k_means(const float* __restrict__ gf, const float* __restrict__ rf) {
    int bc = blockIdx.x;
    int b = bc / NC, c = bc - b * NC;
    const float4* g4 = (const float4*)(gf + (b * NC + c) * NHW);
    const float4* r4 = (const float4*)(rf + (b * NC + c) * NHW);
    const int4* cg4 = (const int4*)(d_cls_g + b * NHW);
    const int4* cr4 = (const int4*)(d_cls_r + b * NHW);
    float sg[NCH], sr[NCH];
#pragma unroll
    for (int k = 0; k < NCH; k++) { sg[k] = 0.f; sr[k] = 0.f; }
    for (int q = threadIdx.x; q < NHW / 4; q += 256) {
        float4 vg = g4[q], vr = r4[q];
        int4 kg = cg4[q], kr = cr4[q];
#pragma unroll
        for (int k = 0; k < NCH; k++) {
            sg[k] += (kg.x == k) ? vg.x : 0.f;
            sg[k] += (kg.y == k) ? vg.y : 0.f;
            sg[k] += (kg.z == k) ? vg.z : 0.f;
            sg[k] += (kg.w == k) ? vg.w : 0.f;
            sr[k] += (kr.x == k) ? vr.x : 0.f;
            sr[k] += (kr.y == k) ? vr.y : 0.f;
            sr[k] += (kr.z == k) ? vr.z : 0.f;
            sr[k] += (kr.w == k) ? vr.w : 0.f;
        }
    }
#pragma unroll
    for (int k = 0; k < NCH; k++) {
#pragma unroll
        for (int off = 16; off; off >>= 1) {
            sg[k] += __shfl_xor_sync(0xffffffffu, sg[k], off);
            sr[k] += __shfl_xor_sync(0xffffffffu, sr[k], off);
        }
    }
    __shared__ float sm[8][2 * NCH];
    int lane = threadIdx.x & 31, w = threadIdx.x >> 5;
    if (lane == 0) {
#pragma unroll
        for (int k = 0; k < NCH; k++) { sm[w][k] = sg[k]; sm[w][NCH + k] = sr[k]; }
    }
    __syncthreads();
    if (threadIdx.x < 2 * NCH) {
        float t = 0.f;
#pragma unroll
        for (int i = 0; i < 8; i++) t += sm[i][threadIdx.x];
        int k = threadIdx.x % NCH;
        bool isr = threadIdx.x >= NCH;
        int cnt = isr ? d_cnt_r[b * NCH + k] : d_cnt_g[b * NCH + k];
        float mean = t / fmaxf((float)cnt, 1.f);
        if (isr) d_mean_r[(b * NCH + k) * NC + c] = mean;
        else     d_mean_g[(b * NCH + k) * NC + c] = mean;
    }
}

// ---------------- kernel 4: normalize + transpose (g/r split by grid.z) ----------------
__global__ void __launch_bounds__(512) k_normalize(const float* __restrict__ gf, const float* __restrict__ rf) {
    __shared__ float tile[NC][33];
    int b = blockIdx.y;
    int p = blockIdx.z;
    int n0 = blockIdx.x * 32;
    int tid = threadIdx.x, lane = tid & 31, w = tid >> 5;
    const float* f   = (p == 0 ? gf : rf) + b * NC * NHW;
    const int*  cls  = (p == 0 ? d_cls_g : d_cls_r) + b * NHW;
    const float* mn  = (p == 0 ? d_mean_g : d_mean_r) + b * NCH * NC;
    float* outp      = (p == 0 ? d_gn : d_rn) + b * NHW * NC;
    // fill: 256 rows x 8 float4 = 2048 vec loads, 4 per thread
#pragma unroll
    for (int it = 0; it < 4; it++) {
        int idx = tid + it * 512;
        int c = idx >> 3, q = idx & 7;
        float4 v = ((const float4*)(f + c * NHW + n0))[q];
        tile[c][q * 4 + 0] = v.x;
        tile[c][q * 4 + 1] = v.y;
        tile[c][q * 4 + 2] = v.z;
        tile[c][q * 4 + 3] = v.w;
    }
    __syncthreads();
#pragma unroll
    for (int q = 0; q < 2; q++) {
        int nn = w * 2 + q;
        int n = n0 + nn;
        int k = cls[n];
        const float* mk = mn + k * NC;
        float bar[8]; float ss = 0.f;
#pragma unroll
        for (int t = 0; t < 8; t++) {
            int c = lane + 32 * t;
            float v = tile[c][nn] - mk[c];
            bar[t] = v;
            ss += v * v;
        }
#pragma unroll
        for (int off = 16; off; off >>= 1) ss += __shfl_xor_sync(0xffffffffu, ss, off);
        float norm = sqrtf(ss);
        float inv = (norm > 0.f) ? (1.f / norm) : 1.f;
#pragma unroll
        for (int t = 0; t < 8; t++)
            outp[n * NC + lane + 32 * t] = bar[t] * inv;
    }
}

// ---------------- kernel 5: attention (4i x 2j register tile, f32x2 fma) ----------------
__global__ void __launch_bounds__(128) k_attn(const float* __restrict__ img, float* __restrict__ out) {
    extern __shared__ __align__(16) float smem_dyn[];
    float* rn_s  = smem_dyn;                 // TJ * RSTR
    float* gn_s  = rn_s + TJ * RSTR;         // TI * NC
    float* img_s = gn_s + TI * NC;           // TJ * 3 (j-major: img_s[cc*TJ + jj])
    int*   s_jl  = (int*)(img_s + TJ * 3);   // TJ
    int*   s_pix = s_jl + TJ;                // TI

    int k = blockIdx.y + 1;
    int b = blockIdx.z;
    int cg = d_cnt_g[b * NCH + k], cr = d_cnt_r[b * NCH + k];
    if (cg < 2 || cr < 2) return;

    int tid = threadIdx.x, lane = tid & 31, w = tid >> 5;
    const int* lg = d_list_g + (b * NCH + k) * NHW;
    const int* lr = d_list_r + (b * NCH + k) * NHW;
    const float4* gn4 = (const float4*)(d_gn + b * NHW * NC);
    const float4* rn4 = (const float4*)(d_rn + b * NHW * NC);
    const float* imgb = img + b * 3 * NHW;

    for (int i_base = blockIdx.x * TI; i_base < cg; i_base += GX * TI) {
        __syncthreads();
        if (tid < TI) s_pix[tid] = lg[min(i_base + tid, cg - 1)];
        __syncthreads();
        // gn tile: TI*64 float4 = 1024, 8 per thread
#pragma unroll
        for (int it = 0; it < (TI * 64) / 128; it++) {
            int idx = tid + it * 128;
            int row = idx >> 6, col4 = idx & 63;
            ((float4*)gn_s)[idx] = gn4[s_pix[row] * 64 + col4];
        }

        float m[TIW], sden[TIW], a0[TIW], a1[TIW], a2[TIW];
#pragma unroll
        for (int ii = 0; ii < TIW; ii++) { m[ii] = -1e30f; sden[ii] = 0.f; a0[ii] = 0.f; a1[ii] = 0.f; a2[ii] = 0.f; }

        for (int j0 = 0; j0 < cr; j0 += TJ) {
            __syncthreads();
            if (tid < TJ) s_jl[tid] = (j0 + tid < cr) ? lr[j0 + tid] : -1;
            __syncthreads();
            // rn tile: TJ*64 float4 = 4096, 32 per thread
#pragma unroll
            for (int it = 0; it < (TJ * 64) / 128; it++) {
                int idx = tid + it * 128;
                int row = idx >> 6, col4 = idx & 63;
                int jp = s_jl[row];
                float4 v = (jp >= 0) ? rn4[jp * 64 + col4] : make_float4(0.f, 0.f, 0.f, 0.f);
                *(float4*)(rn_s + row * RSTR + col4 * 4) = v;
            }
            // img tile (j-major): 192 values
            {
                int idx = tid;
#pragma unroll
                for (int it = 0; it < 2; it++, idx += 128) {
                    if (idx < TJ * 3) {
                        int cc = idx >> 6, jj = idx & 63;
                        int jp = s_jl[jj];
                        img_s[cc * TJ + jj] = (jp >= 0) ? imgb[cc * NHW + jp] : 0.f;
                    }
                }
            }
            __syncthreads();

            // dot: 4 i (w*4+ii) x 2 j (lane, lane+32), packed f32x2
            unsigned long long accA[TIW][2], accB[TIW][2];
#pragma unroll
            for (int ii = 0; ii < TIW; ii++) { accA[ii][0]=0; accA[ii][1]=0; accB[ii][0]=0; accB[ii][1]=0; }
            const ulonglong2* r0p = (const ulonglong2*)(rn_s + lane * RSTR);
            const ulonglong2* r1p = (const ulonglong2*)(rn_s + (lane + 32) * RSTR);
#pragma unroll 4
            for (int c4 = 0; c4 < NC / 4; c4++) {
                ulonglong2 r0 = r0p[c4];
                ulonglong2 r1 = r1p[c4];
#pragma unroll
                for (int ii = 0; ii < TIW; ii++) {
                    ulonglong2 g = ((const ulonglong2*)(gn_s + (w * TIW + ii) * NC))[c4];
                    fma2(accA[ii][0], r0.x, g.x);
                    fma2(accB[ii][0], r0.y, g.y);
                    fma2(accA[ii][1], r1.x, g.x);
                    fma2(accB[ii][1], r1.y, g.y);
                }
            }
            bool v0 = (j0 + lane) < cr;
            bool v1 = (j0 + lane + 32) < cr;
            float i00 = img_s[0 * TJ + lane], i01 = img_s[0 * TJ + lane + 32];
            float i10 = img_s[1 * TJ + lane], i11 = img_s[1 * TJ + lane + 32];
            float i20 = img_s[2 * TJ + lane], i21 = img_s[2 * TJ + lane + 32];
#pragma unroll
            for (int ii = 0; ii < TIW; ii++) {
                float dA = hsum2(accA[ii][0], accB[ii][0]);
                float dB = hsum2(accA[ii][1], accB[ii][1]);
                float nm = m[ii];
                if (v0) nm = fmaxf(nm, dA);
                if (v1) nm = fmaxf(nm, dB);
                float sc = __expf(m[ii] - nm);
                float e0 = v0 ? __expf(dA - nm) : 0.f;
                float e1 = v1 ? __expf(dB - nm) : 0.f;
                sden[ii] = sden[ii] * sc + e0 + e1;
                a0[ii] = a0[ii] * sc + e0 * i00 + e1 * i01;
                a1[ii] = a1[ii] * sc + e0 * i10 + e1 * i11;
                a2[ii] = a2[ii] * sc + e0 * i20 + e1 * i21;
                m[ii] = nm;
            }
        }

        // cross-lane merge, then write
#pragma unroll
        for (int ii = 0; ii < TIW; ii++) {
            float m_ = m[ii], s_ = sden[ii], x = a0[ii], y = a1[ii], z = a2[ii];
#pragma unroll
            for (int off = 16; off; off >>= 1) {
                float m2 = __shfl_xor_sync(0xffffffffu, m_, off);
                float s2 = __shfl_xor_sync(0xffffffffu, s_, off);
                float x2 = __shfl_xor_sync(0xffffffffu, x, off);
                float y2 = __shfl_xor_sync(0xffffffffu, y, off);
                float z2 = __shfl_xor_sync(0xffffffffu, z, off);
                float M  = fmaxf(m_, m2);
                float c1 = __expf(m_ - M), c2 = __expf(m2 - M);
                s_ = s_ * c1 + s2 * c2;
                x  = x  * c1 + x2 * c2;
                y  = y  * c1 + y2 * c2;
                z  = z  * c1 + z2 * c2;
                m_ = M;
            }
            int ig = i_base + w * TIW + ii;
            if (lane == 0 && ig < cg) {
                int pix = s_pix[w * TIW + ii];
                float inv = 1.f / s_;
                out[b * 3 * NHW + 0 * NHW + pix] = x * inv;
                out[b * 3 * NHW + 1 * NHW + pix] = y * inv;
                out[b * 3 * NHW + 2 * NHW + pix] = z * inv;
            }
        }
    }
}

// ---------------- launch ----------------
extern "C" void kernel_launch(void* const* d_in, const int* in_sizes, int n_in,
                              void* d_out, int out_size) {
    (void)in_sizes; (void)n_in; (void)out_size;
    const float* gf  = (const float*)d_in[0];
    const float* rf  = (const float*)d_in[1];
    const float* img = (const float*)d_in[2];
    const float* gl  = (const float*)d_in[3];
    const float* rl  = (const float*)d_in[4];
    float* out = (float*)d_out;

    cudaFuncSetAttribute(k_attn, cudaFuncAttributeMaxDynamicSharedMemorySize, ATTN_SMEM);

    k_classify<<<(NB * NHW / 4 + 255) / 256, 256>>>(gl, rl, out);
    k_lists<<<dim3(NCH, NB), 512>>>();
    k_means<<<NB * NC, 256>>>(gf, rf);
    k_normalize<<<dim3(NHW / 32, NB, 2), 512>>>(gf, rf);
    k_attn<<<dim3(GX, NCH - 1, NB), 128, ATTN_SMEM>>>(img, out);
}

// round 4
// speedup vs baseline: 2.5338x; 1.1504x over previous
#include <cuda_runtime.h>
#include <math.h>

#define NB   2
#define NC   256
#define NHW  2304     // 48*48
#define NCH  12

#define TI   16       // gray pixels per attention block
#define TIW  4        // gray pixels per warp
#define TJ   64       // rgb pixels per smem tile
#define RSTR 260      // padded row stride (floats): bank step 4 per row -> conflict-free LDS.128
#define GX   16       // attention grid.x (stride loop handles overflow)

#define ATTN_SMEM (TJ*RSTR*4 + TI*NC*4 + TJ*3*4 + TJ*4 + TI*4)

// ---------------- scratch ----------------
__device__ int   d_cls_g[NB * NHW];
__device__ int   d_cls_r[NB * NHW];
__device__ int   d_list_g[NB * NCH * NHW];
__device__ int   d_list_r[NB * NCH * NHW];
__device__ int   d_cnt_g[NB * NCH];
__device__ int   d_cnt_r[NB * NCH];
__device__ float d_sum_g[NB * NCH * NC];   // class-masked channel SUMS (divide later)
__device__ float d_sum_r[NB * NCH * NC];
__device__ float d_gn[NB * NHW * NC];      // unit vectors, [b][n][c]
__device__ float d_rn[NB * NHW * NC];

// packed f32x2 helpers
__device__ __forceinline__ void fma2(unsigned long long& d, unsigned long long a, unsigned long long b) {
    asm("fma.rn.f32x2 %0, %1, %2, %0;" : "+l"(d) : "l"(a), "l"(b));
}
__device__ __forceinline__ float hsum2(unsigned long long a, unsigned long long b) {
    unsigned long long s;
    asm("add.rn.f32x2 %0, %1, %2;" : "=l"(s) : "l"(a), "l"(b));
    float lo, hi;
    asm("mov.b64 {%0, %1}, %2;" : "=f"(lo), "=f"(hi) : "l"(s));
    return lo + hi;
}

// ---------------- kernel 1: classify (per-pixel) + init canvas ----------------
__global__ void __launch_bounds__(256) k_classify(const float* __restrict__ gl,
                                                  const float* __restrict__ rl,
                                                  float* __restrict__ out) {
    int idx = blockIdx.x * 256 + threadIdx.x;          // 0 .. NB*NHW-1 (exact grid)
    // canvas init: 3 floats per thread covers NB*3*NHW
    out[idx]            = -1.0f;
    out[idx + NB * NHW]     = -1.0f;
    out[idx + 2 * NB * NHW] = -1.0f;

    int b = idx / NHW, n = idx - b * NHW;
    int kg = 0, kr = 0;
#pragma unroll
    for (int k = 0; k < NCH; k++) {
        if (gl[(b * NCH + k) * NHW + n] > 0.5f) kg = k;
        if (rl[(b * NCH + k) * NHW + n] > 0.5f) kr = k;
    }
    d_cls_g[idx] = kg;
    d_cls_r[idx] = kr;
}

// ---------------- kernel 2: fused lists (blocks 0..23) + masked sums (blocks 24..535) ----------------
__global__ void __launch_bounds__(512) k_prep(const float* __restrict__ gf, const float* __restrict__ rf) {
    int tid = threadIdx.x, lane = tid & 31, w = tid >> 5;

    if (blockIdx.x < NB * NCH) {
        // ---- ordered compaction ----
        int bk = blockIdx.x;
        int b = bk / NCH, k = bk - b * NCH;
        __shared__ int s_wsum[16];
        const int* clsg = d_cls_g + b * NHW;
        const int* clsr = d_cls_r + b * NHW;
        int* lg = d_list_g + (b * NCH + k) * NHW;
        int* lr = d_list_r + (b * NCH + k) * NHW;
        int base_g = 0, base_r = 0;
        for (int n0 = 0; n0 < NHW; n0 += 512) {
            int n = n0 + tid;
            int fg = (n < NHW) && (clsg[n] == k);
            unsigned bal = __ballot_sync(0xffffffffu, fg);
            int wp = __popc(bal & ((1u << lane) - 1u));
            if (lane == 0) s_wsum[w] = __popc(bal);
            __syncthreads();
            int woff = 0, tot = 0;
#pragma unroll
            for (int i = 0; i < 16; i++) { int v = s_wsum[i]; if (i < w) woff += v; tot += v; }
            if (fg) lg[base_g + woff + wp] = n;
            base_g += tot;
            __syncthreads();
            int fr = (n < NHW) && (clsr[n] == k);
            bal = __ballot_sync(0xffffffffu, fr);
            wp = __popc(bal & ((1u << lane) - 1u));
            if (lane == 0) s_wsum[w] = __popc(bal);
            __syncthreads();
            woff = 0; tot = 0;
#pragma unroll
            for (int i = 0; i < 16; i++) { int v = s_wsum[i]; if (i < w) woff += v; tot += v; }
            if (fr) lr[base_r + woff + wp] = n;
            base_r += tot;
            __syncthreads();
        }
        if (tid == 0) { d_cnt_g[b * NCH + k] = base_g; d_cnt_r[b * NCH + k] = base_r; }
    } else {
        // ---- per-(b,c) class-masked sums over pixels ----
        int bc = blockIdx.x - NB * NCH;
        int b = bc >> 8, c = bc & 255;
        const float4* g4 = (const float4*)(gf + (b * NC + c) * NHW);
        const float4* r4 = (const float4*)(rf + (b * NC + c) * NHW);
        const int4* cg4 = (const int4*)(d_cls_g + b * NHW);
        const int4* cr4 = (const int4*)(d_cls_r + b * NHW);
        float sg[NCH], sr[NCH];
#pragma unroll
        for (int k = 0; k < NCH; k++) { sg[k] = 0.f; sr[k] = 0.f; }
        for (int q = tid; q < NHW / 4; q += 512) {
            float4 vg = g4[q], vr = r4[q];
            int4 kg = cg4[q], kr = cr4[q];
#pragma unroll
            for (int k = 0; k < NCH; k++) {
                sg[k] += (kg.x == k) ? vg.x : 0.f;
                sg[k] += (kg.y == k) ? vg.y : 0.f;
                sg[k] += (kg.z == k) ? vg.z : 0.f;
                sg[k] += (kg.w == k) ? vg.w : 0.f;
                sr[k] += (kr.x == k) ? vr.x : 0.f;
                sr[k] += (kr.y == k) ? vr.y : 0.f;
                sr[k] += (kr.z == k) ? vr.z : 0.f;
                sr[k] += (kr.w == k) ? vr.w : 0.f;
            }
        }
#pragma unroll
        for (int k = 0; k < NCH; k++) {
#pragma unroll
            for (int off = 16; off; off >>= 1) {
                sg[k] += __shfl_xor_sync(0xffffffffu, sg[k], off);
                sr[k] += __shfl_xor_sync(0xffffffffu, sr[k], off);
            }
        }
        __shared__ float sm[16][2 * NCH];
        if (lane == 0) {
#pragma unroll
            for (int k = 0; k < NCH; k++) { sm[w][k] = sg[k]; sm[w][NCH + k] = sr[k]; }
        }
        __syncthreads();
        if (tid < 2 * NCH) {
            float t = 0.f;
#pragma unroll
            for (int i = 0; i < 16; i++) t += sm[i][tid];
            int k = tid % NCH;
            if (tid >= NCH) d_sum_r[(b * NCH + k) * NC + c] = t;
            else            d_sum_g[(b * NCH + k) * NC + c] = t;
        }
    }
}

// ---------------- kernel 3: normalize + transpose (256 threads; g/r split by grid.z) ----------------
__global__ void __launch_bounds__(256) k_normalize(const float* __restrict__ gf, const float* __restrict__ rf) {
    __shared__ float tile[NC][33];
    int b = blockIdx.y;
    int p = blockIdx.z;
    int n0 = blockIdx.x * 32;
    int tid = threadIdx.x, lane = tid & 31, w = tid >> 5;
    const float* f   = (p == 0 ? gf : rf) + b * NC * NHW;
    const int*  cls  = (p == 0 ? d_cls_g : d_cls_r) + b * NHW;
    const float* sums = (p == 0 ? d_sum_g : d_sum_r) + b * NCH * NC;
    const int*  cnts = (p == 0 ? d_cnt_g : d_cnt_r) + b * NCH;
    float* outp      = (p == 0 ? d_gn : d_rn) + b * NHW * NC;
    // fill: 2048 float4 loads, 8 per thread (high MLP)
#pragma unroll
    for (int it = 0; it < 8; it++) {
        int idx = tid + it * 256;
        int c = idx >> 3, q = idx & 7;
        float4 v = ((const float4*)(f + c * NHW + n0))[q];
        tile[c][q * 4 + 0] = v.x;
        tile[c][q * 4 + 1] = v.y;
        tile[c][q * 4 + 2] = v.z;
        tile[c][q * 4 + 3] = v.w;
    }
    __syncthreads();
#pragma unroll
    for (int q = 0; q < 4; q++) {
        int nn = w * 4 + q;
        int n = n0 + nn;
        int k = cls[n];
        float invc = 1.0f / fmaxf((float)cnts[k], 1.0f);
        const float* mk = sums + k * NC;
        float bar[8]; float ss = 0.f;
#pragma unroll
        for (int t = 0; t < 8; t++) {
            int c = lane + 32 * t;
            float v = tile[c][nn] - mk[c] * invc;
            bar[t] = v;
            ss += v * v;
        }
#pragma unroll
        for (int off = 16; off; off >>= 1) ss += __shfl_xor_sync(0xffffffffu, ss, off);
        float norm = sqrtf(ss);
        float inv = (norm > 0.f) ? (1.f / norm) : 1.f;
#pragma unroll
        for (int t = 0; t < 8; t++)
            outp[n * NC + lane + 32 * t] = bar[t] * inv;
    }
}

// ---------------- kernel 4: attention (4i x 2j register tile, f32x2 fma) ----------------
__global__ void __launch_bounds__(128) k_attn(const float* __restrict__ img, float* __restrict__ out) {
    extern __shared__ __align__(16) float smem_dyn[];
    float* rn_s  = smem_dyn;                 // TJ * RSTR
    float* gn_s  = rn_s + TJ * RSTR;         // TI * NC
    float* img_s = gn_s + TI * NC;           // TJ * 3 (j-major)
    int*   s_jl  = (int*)(img_s + TJ * 3);   // TJ
    int*   s_pix = s_jl + TJ;                // TI

    int k = blockIdx.y + 1;
    int b = blockIdx.z;
    int cg = d_cnt_g[b * NCH + k], cr = d_cnt_r[b * NCH + k];
    if (cg < 2 || cr < 2) return;

    int tid = threadIdx.x, lane = tid & 31, w = tid >> 5;
    const int* lg = d_list_g + (b * NCH + k) * NHW;
    const int* lr = d_list_r + (b * NCH + k) * NHW;
    const float4* gn4 = (const float4*)(d_gn + b * NHW * NC);
    const float4* rn4 = (const float4*)(d_rn + b * NHW * NC);
    const float* imgb = img + b * 3 * NHW;

    for (int i_base = blockIdx.x * TI; i_base < cg; i_base += GX * TI) {
        __syncthreads();
        if (tid < TI) s_pix[tid] = lg[min(i_base + tid, cg - 1)];
        __syncthreads();
#pragma unroll
        for (int it = 0; it < (TI * 64) / 128; it++) {
            int idx = tid + it * 128;
            int row = idx >> 6, col4 = idx & 63;
            ((float4*)gn_s)[idx] = gn4[s_pix[row] * 64 + col4];
        }

        float m[TIW], sden[TIW], a0[TIW], a1[TIW], a2[TIW];
#pragma unroll
        for (int ii = 0; ii < TIW; ii++) { m[ii] = -1e30f; sden[ii] = 0.f; a0[ii] = 0.f; a1[ii] = 0.f; a2[ii] = 0.f; }

        for (int j0 = 0; j0 < cr; j0 += TJ) {
            __syncthreads();
            if (tid < TJ) s_jl[tid] = (j0 + tid < cr) ? lr[j0 + tid] : -1;
            __syncthreads();
#pragma unroll
            for (int it = 0; it < (TJ * 64) / 128; it++) {
                int idx = tid + it * 128;
                int row = idx >> 6, col4 = idx & 63;
                int jp = s_jl[row];
                float4 v = (jp >= 0) ? rn4[jp * 64 + col4] : make_float4(0.f, 0.f, 0.f, 0.f);
                *(float4*)(rn_s + row * RSTR + col4 * 4) = v;
            }
            {
                int idx = tid;
#pragma unroll
                for (int it = 0; it < 2; it++, idx += 128) {
                    if (idx < TJ * 3) {
                        int cc = idx >> 6, jj = idx & 63;
                        int jp = s_jl[jj];
                        img_s[cc * TJ + jj] = (jp >= 0) ? imgb[cc * NHW + jp] : 0.f;
                    }
                }
            }
            __syncthreads();

            unsigned long long accA[TIW][2], accB[TIW][2];
#pragma unroll
            for (int ii = 0; ii < TIW; ii++) { accA[ii][0]=0; accA[ii][1]=0; accB[ii][0]=0; accB[ii][1]=0; }
            const ulonglong2* r0p = (const ulonglong2*)(rn_s + lane * RSTR);
            const ulonglong2* r1p = (const ulonglong2*)(rn_s + (lane + 32) * RSTR);
#pragma unroll 4
            for (int c4 = 0; c4 < NC / 4; c4++) {
                ulonglong2 r0 = r0p[c4];
                ulonglong2 r1 = r1p[c4];
#pragma unroll
                for (int ii = 0; ii < TIW; ii++) {
                    ulonglong2 g = ((const ulonglong2*)(gn_s + (w * TIW + ii) * NC))[c4];
                    fma2(accA[ii][0], r0.x, g.x);
                    fma2(accB[ii][0], r0.y, g.y);
                    fma2(accA[ii][1], r1.x, g.x);
                    fma2(accB[ii][1], r1.y, g.y);
                }
            }
            bool v0 = (j0 + lane) < cr;
            bool v1 = (j0 + lane + 32) < cr;
            float i00 = img_s[0 * TJ + lane], i01 = img_s[0 * TJ + lane + 32];
            float i10 = img_s[1 * TJ + lane], i11 = img_s[1 * TJ + lane + 32];
            float i20 = img_s[2 * TJ + lane], i21 = img_s[2 * TJ + lane + 32];
#pragma unroll
            for (int ii = 0; ii < TIW; ii++) {
                float dA = hsum2(accA[ii][0], accB[ii][0]);
                float dB = hsum2(accA[ii][1], accB[ii][1]);
                float nm = m[ii];
                if (v0) nm = fmaxf(nm, dA);
                if (v1) nm = fmaxf(nm, dB);
                float sc = __expf(m[ii] - nm);
                float e0 = v0 ? __expf(dA - nm) : 0.f;
                float e1 = v1 ? __expf(dB - nm) : 0.f;
                sden[ii] = sden[ii] * sc + e0 + e1;
                a0[ii] = a0[ii] * sc + e0 * i00 + e1 * i01;
                a1[ii] = a1[ii] * sc + e0 * i10 + e1 * i11;
                a2[ii] = a2[ii] * sc + e0 * i20 + e1 * i21;
                m[ii] = nm;
            }
        }

#pragma unroll
        for (int ii = 0; ii < TIW; ii++) {
            float m_ = m[ii], s_ = sden[ii], x = a0[ii], y = a1[ii], z = a2[ii];
#pragma unroll
            for (int off = 16; off; off >>= 1) {
                float m2 = __shfl_xor_sync(0xffffffffu, m_, off);
                float s2 = __shfl_xor_sync(0xffffffffu, s_, off);
                float x2 = __shfl_xor_sync(0xffffffffu, x, off);
                float y2 = __shfl_xor_sync(0xffffffffu, y, off);
                float z2 = __shfl_xor_sync(0xffffffffu, z, off);
                float M  = fmaxf(m_, m2);
                float c1 = __expf(m_ - M), c2 = __expf(m2 - M);
                s_ = s_ * c1 + s2 * c2;
                x  = x  * c1 + x2 * c2;
                y  = y  * c1 + y2 * c2;
                z  = z  * c1 + z2 * c2;
                m_ = M;
            }
            int ig = i_base + w * TIW + ii;
            if (lane == 0 && ig < cg) {
                int pix = s_pix[w * TIW + ii];
                float inv = 1.f / s_;
                out[b * 3 * NHW + 0 * NHW + pix] = x * inv;
                out[b * 3 * NHW + 1 * NHW + pix] = y * inv;
                out[b * 3 * NHW + 2 * NHW + pix] = z * inv;
            }
        }
    }
}

// ---------------- launch ----------------
extern "C" void kernel_launch(void* const* d_in, const int* in_sizes, int n_in,
                              void* d_out, int out_size) {
    (void)in_sizes; (void)n_in; (void)out_size;
    const float* gf  = (const float*)d_in[0];
    const float* rf  = (const float*)d_in[1];
    const float* img = (const float*)d_in[2];
    const float* gl  = (const float*)d_in[3];
    const float* rl  = (const float*)d_in[4];
    float* out = (float*)d_out;

    cudaFuncSetAttribute(k_attn, cudaFuncAttributeMaxDynamicSharedMemorySize, ATTN_SMEM);

    k_classify<<<NB * NHW / 256, 256>>>(gl, rl, out);
    k_prep<<<NB * NCH + NB * NC, 512>>>(gf, rf);
    k_normalize<<<dim3(NHW / 32, NB, 2), 256>>>(gf, rf);
    k_attn<<<dim3(GX, NCH - 1, NB), 128, ATTN_SMEM>>>(img, out);
}